// round 1
// baseline (speedup 1.0000x reference)
#include <cuda_runtime.h>
#include <math.h>
#include <stdint.h>
#include <stddef.h>

#define N0V 50000
#define N1V 150000
#define N2V 100000
#define DV  256

// ---- scratch (device globals: no allocation allowed) ----
__device__ float g_xj0[(size_t)N0V * DV];
__device__ float g_xj1[(size_t)N1V * DV];
__device__ float g_xj2[(size_t)N2V * DV];
__device__ float g_ai0[N0V];
__device__ float g_aj0[N0V];
__device__ float g_aj1[N1V];
__device__ float g_aj2[N2V];

// ============================================================
// GEMM: Y[M,256] = relu(X[M,256] @ W[256,256]^T + b)
// Classic 128x128x16 SGEMM, 8x8 microtile, 256 threads.
// ============================================================
#define BM 128
#define BN 128
#define BK 16
#define PADF 4   // smem row padding (keeps 16B alignment: 132*4B % 16 == 0)

__global__ __launch_bounds__(256, 2)
void gemm_relu_kernel(const float* __restrict__ X,
                      const float* __restrict__ W,
                      const float* __restrict__ bias,
                      float* __restrict__ Y,
                      int M)
{
    __shared__ float As[BK][BM + PADF];
    __shared__ float Bs[BK][BN + PADF];

    const int t  = threadIdx.x;
    const int tx = t & 15;        // 0..15  (n dimension)
    const int ty = t >> 4;        // 0..15  (m dimension)
    const int bm = blockIdx.x * BM;
    const int bn = blockIdx.y * BN;

    float acc[8][8];
#pragma unroll
    for (int i = 0; i < 8; i++)
#pragma unroll
        for (int j = 0; j < 8; j++) acc[i][j] = 0.0f;

    for (int kt = 0; kt < DV; kt += BK) {
        // ---- load tiles (512 float4 per operand, 2 per thread) ----
#pragma unroll
        for (int l = 0; l < 2; l++) {
            const int i   = t + l * 256;
            const int row = i >> 2;       // 0..127
            const int k4  = i & 3;        // float4 index within BK
            // A tile (guard M edge, zero-fill)
            float4 va = make_float4(0.f, 0.f, 0.f, 0.f);
            const int gr = bm + row;
            if (gr < M)
                va = *(const float4*)(X + (size_t)gr * DV + kt + k4 * 4);
            As[k4 * 4 + 0][row] = va.x;
            As[k4 * 4 + 1][row] = va.y;
            As[k4 * 4 + 2][row] = va.z;
            As[k4 * 4 + 3][row] = va.w;
            // B tile (W has exactly 256 rows; bn+row always < 256)
            const float4 vb = *(const float4*)(W + (size_t)(bn + row) * DV + kt + k4 * 4);
            Bs[k4 * 4 + 0][row] = vb.x;
            Bs[k4 * 4 + 1][row] = vb.y;
            Bs[k4 * 4 + 2][row] = vb.z;
            Bs[k4 * 4 + 3][row] = vb.w;
        }
        __syncthreads();

        // ---- compute ----
#pragma unroll
        for (int k = 0; k < BK; k++) {
            const float4 a0 = *(const float4*)&As[k][ty * 4];
            const float4 a1 = *(const float4*)&As[k][64 + ty * 4];
            const float4 b0 = *(const float4*)&Bs[k][tx * 4];
            const float4 b1 = *(const float4*)&Bs[k][64 + tx * 4];
            const float av[8] = {a0.x, a0.y, a0.z, a0.w, a1.x, a1.y, a1.z, a1.w};
            const float bv[8] = {b0.x, b0.y, b0.z, b0.w, b1.x, b1.y, b1.z, b1.w};
#pragma unroll
            for (int i = 0; i < 8; i++)
#pragma unroll
                for (int j = 0; j < 8; j++)
                    acc[i][j] = fmaf(av[i], bv[j], acc[i][j]);
        }
        __syncthreads();
    }

    // ---- epilogue: +bias, relu, store ----
    const int n0 = bn + tx * 4;
    const int n1 = bn + 64 + tx * 4;
    const float4 bias0 = *(const float4*)(bias + n0);
    const float4 bias1 = *(const float4*)(bias + n1);
#pragma unroll
    for (int i = 0; i < 8; i++) {
        const int gm = bm + ((i < 4) ? (ty * 4 + i) : (64 + ty * 4 + (i - 4)));
        if (gm >= M) continue;
        float4 r0, r1;
        r0.x = fmaxf(acc[i][0] + bias0.x, 0.f);
        r0.y = fmaxf(acc[i][1] + bias0.y, 0.f);
        r0.z = fmaxf(acc[i][2] + bias0.z, 0.f);
        r0.w = fmaxf(acc[i][3] + bias0.w, 0.f);
        r1.x = fmaxf(acc[i][4] + bias1.x, 0.f);
        r1.y = fmaxf(acc[i][5] + bias1.y, 0.f);
        r1.z = fmaxf(acc[i][6] + bias1.z, 0.f);
        r1.w = fmaxf(acc[i][7] + bias1.w, 0.f);
        *(float4*)(Y + (size_t)gm * DV + n0) = r0;
        *(float4*)(Y + (size_t)gm * DV + n1) = r1;
    }
}

// ============================================================
// Row dot: a[row] = Y[row,:] . aw + ab   (one warp per row)
// ============================================================
__global__ void rowdot_kernel(const float* __restrict__ Y,
                              const float* __restrict__ aw,
                              const float* __restrict__ ab,
                              float* __restrict__ outA,
                              int M)
{
    const int row  = (int)((blockIdx.x * (unsigned)blockDim.x + threadIdx.x) >> 5);
    const int lane = threadIdx.x & 31;
    if (row >= M) return;
    const float4* y4 = (const float4*)(Y + (size_t)row * DV);
    const float4* a4 = (const float4*)aw;
    float s = 0.f;
#pragma unroll
    for (int i = lane; i < 64; i += 32) {
        const float4 v = __ldg(y4 + i);
        const float4 a = __ldg(a4 + i);
        s += v.x * a.x + v.y * a.y + v.z * a.z + v.w * a.w;
    }
#pragma unroll
    for (int o = 16; o > 0; o >>= 1) s += __shfl_xor_sync(0xffffffffu, s, o);
    if (lane == 0) outA[row] = s + __ldg(ab);
}

// ============================================================
// Edge aggregation: out[r,:] += sigmoid(ai[r]+aj[c]) * xj[c,:]
// One warp per edge. Vector reductions (red.global.add.v4.f32)
// cut atomic count 4x vs scalar atomicAdd.
// ============================================================
__device__ __forceinline__ void red_add_v4(float* p, float4 v)
{
    asm volatile("red.global.add.v4.f32 [%0], {%1, %2, %3, %4};"
                 :: "l"(p), "f"(v.x), "f"(v.y), "f"(v.z), "f"(v.w)
                 : "memory");
}

__global__ void edge_kernel(const int* __restrict__ rows,
                            const int* __restrict__ cols,
                            const float* __restrict__ ai,
                            const float* __restrict__ aj,
                            const float* __restrict__ xj,
                            float* __restrict__ out,
                            int E)
{
    const int e    = (int)((blockIdx.x * (unsigned)blockDim.x + threadIdx.x) >> 5);
    const int lane = threadIdx.x & 31;
    if (e >= E) return;

    const int r = __ldg(rows + e);
    const int c = __ldg(cols + e);
    const float s   = __ldg(ai + r) + __ldg(aj + c);
    const float att = 1.0f / (1.0f + __expf(-s));

    const float4* src = (const float4*)(xj + (size_t)c * DV);
    float* dst = out + (size_t)r * DV;

    float4 v0 = __ldg(src + lane);
    float4 v1 = __ldg(src + 32 + lane);
    v0.x *= att; v0.y *= att; v0.z *= att; v0.w *= att;
    v1.x *= att; v1.y *= att; v1.z *= att; v1.w *= att;

    red_add_v4(dst + lane * 4, v0);
    red_add_v4(dst + 128 + lane * 4, v1);
}

// ============================================================
// Launch
// ============================================================
extern "C" void kernel_launch(void* const* d_in, const int* in_sizes, int n_in,
                              void* d_out, int out_size)
{
    const float* x0    = (const float*)d_in[0];
    const float* x1    = (const float*)d_in[1];
    const float* x2    = (const float*)d_in[2];
    const int*   rows0 = (const int*)d_in[3];
    const int*   cols0 = (const int*)d_in[4];
    const int*   rows1 = (const int*)d_in[5];
    const int*   cols1 = (const int*)d_in[6];
    const int*   rows2 = (const int*)d_in[7];
    const int*   cols2 = (const int*)d_in[8];
    const float* W1 = (const float*)d_in[9];
    const float* b1 = (const float*)d_in[10];
    const float* W2 = (const float*)d_in[11];
    const float* b2 = (const float*)d_in[12];
    const float* W3 = (const float*)d_in[13];
    const float* b3 = (const float*)d_in[14];
    const float* W4 = (const float*)d_in[15];
    const float* b4 = (const float*)d_in[16];
    const float* a1w = (const float*)d_in[17];
    const float* a1b = (const float*)d_in[18];
    const float* a2w = (const float*)d_in[19];
    const float* a2b = (const float*)d_in[20];

    const int E0 = in_sizes[3];
    const int E1 = in_sizes[5];
    const int E2 = in_sizes[7];

    float* out = (float*)d_out;

    float *xj0, *xj1, *xj2, *ai0, *aj0, *aj1, *aj2;
    cudaGetSymbolAddress((void**)&xj0, g_xj0);
    cudaGetSymbolAddress((void**)&xj1, g_xj1);
    cudaGetSymbolAddress((void**)&xj2, g_xj2);
    cudaGetSymbolAddress((void**)&ai0, g_ai0);
    cudaGetSymbolAddress((void**)&aj0, g_aj0);
    cudaGetSymbolAddress((void**)&aj1, g_aj1);
    cudaGetSymbolAddress((void**)&aj2, g_aj2);

    // 1) GEMMs. xi_0 goes straight into d_out.
    gemm_relu_kernel<<<dim3((N0V + BM - 1) / BM, 2), 256>>>(x0, W1, b1, out, N0V);
    gemm_relu_kernel<<<dim3((N0V + BM - 1) / BM, 2), 256>>>(x0, W2, b2, xj0, N0V);
    gemm_relu_kernel<<<dim3((N1V + BM - 1) / BM, 2), 256>>>(x1, W3, b3, xj1, N1V);
    gemm_relu_kernel<<<dim3((N2V + BM - 1) / BM, 2), 256>>>(x2, W4, b4, xj2, N2V);

    // 2) attention scalars (one warp per row)
    rowdot_kernel<<<(int)(((size_t)N0V * 32 + 255) / 256), 256>>>(out, a1w, a1b, ai0, N0V);
    rowdot_kernel<<<(int)(((size_t)N0V * 32 + 255) / 256), 256>>>(xj0, a2w, a2b, aj0, N0V);
    rowdot_kernel<<<(int)(((size_t)N1V * 32 + 255) / 256), 256>>>(xj1, a2w, a2b, aj1, N1V);
    rowdot_kernel<<<(int)(((size_t)N2V * 32 + 255) / 256), 256>>>(xj2, a2w, a2b, aj2, N2V);

    // 3) edge aggregations (atomic vector adds into d_out)
    edge_kernel<<<(int)(((size_t)E0 * 32 + 255) / 256), 256>>>(rows0, cols0, ai0, aj0, xj0, out, E0);
    edge_kernel<<<(int)(((size_t)E1 * 32 + 255) / 256), 256>>>(rows1, cols1, ai0, aj1, xj1, out, E1);
    edge_kernel<<<(int)(((size_t)E2 * 32 + 255) / 256), 256>>>(rows2, cols2, ai0, aj2, xj2, out, E2);
}

// round 2
// speedup vs baseline: 1.8626x; 1.8626x over previous
#include <cuda_runtime.h>
#include <math.h>
#include <stdint.h>
#include <stddef.h>

#define N0V 50000
#define N1V 150000
#define N2V 100000
#define DV  256

// ---- scratch (device globals: no allocation allowed) ----
__device__ float g_xj0[(size_t)N0V * DV];
__device__ float g_xj1[(size_t)N1V * DV];
__device__ float g_xj2[(size_t)N2V * DV];
__device__ float g_ai0[N0V];
__device__ float g_aj0[N0V];
__device__ float g_aj1[N1V];
__device__ float g_aj2[N2V];

__device__ __forceinline__ uint32_t f2tf32(float x)
{
    uint32_t r;
    asm("cvt.rna.tf32.f32 %0, %1;" : "=r"(r) : "f"(x));
    return r;
}

// ============================================================
// Tensor-core GEMM: Y[M,256] = relu(X[M,256] @ W[256,256]^T + b)
// Fused: avec[row] (+)= Y[row,:] . aw + ab   (attention scalar)
//
// mma.sync.m16n8k8 tf32. Block 128x128, 8 warps, warp tile 64x32,
// BK=32. grid = (2, M/128) so both N-halves of a row block are
// temporally adjacent (X tile hits L2 on the second block).
// ============================================================
#define BM 128
#define BN 128
#define BK 32
#define SROW 36   // padded smem row stride (floats): conflict-free frag LDS

__global__ __launch_bounds__(256, 2)
void gemm_tf32_kernel(const float* __restrict__ X,
                      const float* __restrict__ W,
                      const float* __restrict__ bias,
                      const float* __restrict__ aw,
                      const float* __restrict__ ab,
                      float* __restrict__ Y,
                      float* __restrict__ avec,
                      int M)
{
    __shared__ uint32_t As[BM * SROW];
    __shared__ uint32_t Bs[BN * SROW];

    const int t    = threadIdx.x;
    const int wid  = t >> 5;
    const int lane = t & 31;
    const int grp  = lane >> 2;   // 0..7
    const int tig  = lane & 3;    // 0..3
    const int warp_m = wid & 1;   // 0..1 -> 64 rows each
    const int warp_n = wid >> 1;  // 0..3 -> 32 cols each
    const int bm = blockIdx.y * BM;
    const int bn = blockIdx.x * BN;

    float acc[4][4][4];
#pragma unroll
    for (int mi = 0; mi < 4; mi++)
#pragma unroll
        for (int nj = 0; nj < 4; nj++)
#pragma unroll
            for (int r = 0; r < 4; r++) acc[mi][nj][r] = 0.0f;

    for (int kt = 0; kt < DV; kt += BK) {
        // ---- load tiles (1024 float4 each, 4 per thread) ----
#pragma unroll
        for (int l = 0; l < 4; l++) {
            const int idx = t + l * 256;
            const int row = idx >> 3;     // 0..127
            const int c4  = idx & 7;      // float4 within BK
            // A (guard M edge)
            float4 va = make_float4(0.f, 0.f, 0.f, 0.f);
            const int gr = bm + row;
            if (gr < M)
                va = *(const float4*)(X + (size_t)gr * DV + kt + c4 * 4);
            uint4 ua;
            ua.x = f2tf32(va.x); ua.y = f2tf32(va.y);
            ua.z = f2tf32(va.z); ua.w = f2tf32(va.w);
            *(uint4*)(As + row * SROW + c4 * 4) = ua;
            // B: W[bn+row][kt + c4*4..]; bn+row < 256 always
            const float4 vb = *(const float4*)(W + (size_t)(bn + row) * DV + kt + c4 * 4);
            uint4 ub;
            ub.x = f2tf32(vb.x); ub.y = f2tf32(vb.y);
            ub.z = f2tf32(vb.z); ub.w = f2tf32(vb.w);
            *(uint4*)(Bs + row * SROW + c4 * 4) = ub;
        }
        __syncthreads();

#pragma unroll
        for (int ks = 0; ks < 4; ks++) {
            const int k0 = ks * 8;
            uint32_t a[4][4], b[4][2];
#pragma unroll
            for (int mi = 0; mi < 4; mi++) {
                const int r = warp_m * 64 + mi * 16 + grp;
                a[mi][0] = As[r * SROW + k0 + tig];
                a[mi][1] = As[(r + 8) * SROW + k0 + tig];
                a[mi][2] = As[r * SROW + k0 + tig + 4];
                a[mi][3] = As[(r + 8) * SROW + k0 + tig + 4];
            }
#pragma unroll
            for (int nj = 0; nj < 4; nj++) {
                const int c = warp_n * 32 + nj * 8 + grp;
                b[nj][0] = Bs[c * SROW + k0 + tig];
                b[nj][1] = Bs[c * SROW + k0 + tig + 4];
            }
#pragma unroll
            for (int mi = 0; mi < 4; mi++)
#pragma unroll
                for (int nj = 0; nj < 4; nj++) {
                    asm volatile(
                        "mma.sync.aligned.m16n8k8.row.col.f32.tf32.tf32.f32 "
                        "{%0,%1,%2,%3}, {%4,%5,%6,%7}, {%8,%9}, {%0,%1,%2,%3};"
                        : "+f"(acc[mi][nj][0]), "+f"(acc[mi][nj][1]),
                          "+f"(acc[mi][nj][2]), "+f"(acc[mi][nj][3])
                        : "r"(a[mi][0]), "r"(a[mi][1]), "r"(a[mi][2]), "r"(a[mi][3]),
                          "r"(b[nj][0]), "r"(b[nj][1]));
                }
        }
        __syncthreads();
    }

    // ---- epilogue: +bias, relu, store, fused attention dot ----
    float awv[4][2], bv[4][2];
#pragma unroll
    for (int nj = 0; nj < 4; nj++) {
        const int col = bn + warp_n * 32 + nj * 8 + 2 * tig;
        const float2 a2 = *(const float2*)(aw + col);
        const float2 b2 = *(const float2*)(bias + col);
        awv[nj][0] = a2.x; awv[nj][1] = a2.y;
        bv[nj][0]  = b2.x; bv[nj][1]  = b2.y;
    }
    const float abv = __ldg(ab);
    const bool add_ab = (blockIdx.x == 0) && (warp_n == 0);

#pragma unroll
    for (int mi = 0; mi < 4; mi++) {
#pragma unroll
        for (int h = 0; h < 2; h++) {       // row grp / grp+8
            const int gr = bm + warp_m * 64 + mi * 16 + grp + h * 8;
            float dp = 0.0f;
            float2 st[4];
#pragma unroll
            for (int nj = 0; nj < 4; nj++) {
                float v0 = fmaxf(acc[mi][nj][h * 2 + 0] + bv[nj][0], 0.f);
                float v1 = fmaxf(acc[mi][nj][h * 2 + 1] + bv[nj][1], 0.f);
                dp += v0 * awv[nj][0] + v1 * awv[nj][1];
                st[nj].x = v0; st[nj].y = v1;
            }
            // reduce dot over the quad (tig = lane&3)
            dp += __shfl_xor_sync(0xffffffffu, dp, 1);
            dp += __shfl_xor_sync(0xffffffffu, dp, 2);
            if (gr < M) {
#pragma unroll
                for (int nj = 0; nj < 4; nj++) {
                    const int col = bn + warp_n * 32 + nj * 8 + 2 * tig;
                    *(float2*)(Y + (size_t)gr * DV + col) = st[nj];
                }
                if (tig == 0)
                    atomicAdd(avec + gr, dp + (add_ab ? abv : 0.0f));
            }
        }
    }
}

// ============================================================
// Zero the attention-scalar accumulators (replay-safe)
// ============================================================
__global__ void zero_avec_kernel(float* a, float* b, float* c, float* d)
{
    const int i = blockIdx.x * blockDim.x + threadIdx.x;
    if (i < N0V) { a[i] = 0.f; b[i] = 0.f; }
    if (i < N1V) c[i] = 0.f;
    if (i < N2V) d[i] = 0.f;
}

// ============================================================
// Edge aggregation: out[r,:] += sigmoid(ai[r]+aj[c]) * xj[c,:]
// One warp per edge; red.global.add.v4.f32.
// ============================================================
__device__ __forceinline__ void red_add_v4(float* p, float4 v)
{
    asm volatile("red.global.add.v4.f32 [%0], {%1, %2, %3, %4};"
                 :: "l"(p), "f"(v.x), "f"(v.y), "f"(v.z), "f"(v.w)
                 : "memory");
}

__global__ void edge_kernel(const int* __restrict__ rows,
                            const int* __restrict__ cols,
                            const float* __restrict__ ai,
                            const float* __restrict__ aj,
                            const float* __restrict__ xj,
                            float* __restrict__ out,
                            int E)
{
    const int e    = (int)((blockIdx.x * (unsigned)blockDim.x + threadIdx.x) >> 5);
    const int lane = threadIdx.x & 31;
    if (e >= E) return;

    const int r = __ldg(rows + e);
    const int c = __ldg(cols + e);
    const float s   = __ldg(ai + r) + __ldg(aj + c);
    const float att = 1.0f / (1.0f + __expf(-s));

    const float4* src = (const float4*)(xj + (size_t)c * DV);
    float* dst = out + (size_t)r * DV;

    float4 v0 = __ldg(src + lane);
    float4 v1 = __ldg(src + 32 + lane);
    v0.x *= att; v0.y *= att; v0.z *= att; v0.w *= att;
    v1.x *= att; v1.y *= att; v1.z *= att; v1.w *= att;

    red_add_v4(dst + lane * 4, v0);
    red_add_v4(dst + 128 + lane * 4, v1);
}

// ============================================================
// Launch
// ============================================================
extern "C" void kernel_launch(void* const* d_in, const int* in_sizes, int n_in,
                              void* d_out, int out_size)
{
    const float* x0    = (const float*)d_in[0];
    const float* x1    = (const float*)d_in[1];
    const float* x2    = (const float*)d_in[2];
    const int*   rows0 = (const int*)d_in[3];
    const int*   cols0 = (const int*)d_in[4];
    const int*   rows1 = (const int*)d_in[5];
    const int*   cols1 = (const int*)d_in[6];
    const int*   rows2 = (const int*)d_in[7];
    const int*   cols2 = (const int*)d_in[8];
    const float* W1 = (const float*)d_in[9];
    const float* b1 = (const float*)d_in[10];
    const float* W2 = (const float*)d_in[11];
    const float* b2 = (const float*)d_in[12];
    const float* W3 = (const float*)d_in[13];
    const float* b3 = (const float*)d_in[14];
    const float* W4 = (const float*)d_in[15];
    const float* b4 = (const float*)d_in[16];
    const float* a1w = (const float*)d_in[17];
    const float* a1b = (const float*)d_in[18];
    const float* a2w = (const float*)d_in[19];
    const float* a2b = (const float*)d_in[20];

    const int E0 = in_sizes[3];
    const int E1 = in_sizes[5];
    const int E2 = in_sizes[7];

    float* out = (float*)d_out;

    float *xj0, *xj1, *xj2, *ai0, *aj0, *aj1, *aj2;
    cudaGetSymbolAddress((void**)&xj0, g_xj0);
    cudaGetSymbolAddress((void**)&xj1, g_xj1);
    cudaGetSymbolAddress((void**)&xj2, g_xj2);
    cudaGetSymbolAddress((void**)&ai0, g_ai0);
    cudaGetSymbolAddress((void**)&aj0, g_aj0);
    cudaGetSymbolAddress((void**)&aj1, g_aj1);
    cudaGetSymbolAddress((void**)&aj2, g_aj2);

    // 0) zero attention accumulators (graph-replay safe)
    zero_avec_kernel<<<(N1V + 255) / 256, 256>>>(ai0, aj0, aj1, aj2);

    // 1) GEMMs (tensor core tf32) with fused attention-scalar dot.
    //    grid = (2 n-halves, m-blocks): n-halves adjacent -> X L2 reuse.
    gemm_tf32_kernel<<<dim3(2, (N0V + BM - 1) / BM), 256>>>(x0, W1, b1, a1w, a1b, out, ai0, N0V);
    gemm_tf32_kernel<<<dim3(2, (N0V + BM - 1) / BM), 256>>>(x0, W2, b2, a2w, a2b, xj0, aj0, N0V);
    gemm_tf32_kernel<<<dim3(2, (N1V + BM - 1) / BM), 256>>>(x1, W3, b3, a2w, a2b, xj1, aj1, N1V);
    gemm_tf32_kernel<<<dim3(2, (N2V + BM - 1) / BM), 256>>>(x2, W4, b4, a2w, a2b, xj2, aj2, N2V);

    // 2) edge aggregations (atomic vector adds into d_out)
    edge_kernel<<<(int)(((size_t)E0 * 32 + 255) / 256), 256>>>(rows0, cols0, ai0, aj0, xj0, out, E0);
    edge_kernel<<<(int)(((size_t)E1 * 32 + 255) / 256), 256>>>(rows1, cols1, ai0, aj1, xj1, out, E1);
    edge_kernel<<<(int)(((size_t)E2 * 32 + 255) / 256), 256>>>(rows2, cols2, ai0, aj2, xj2, out, E2);
}

// round 3
// speedup vs baseline: 2.0661x; 1.1093x over previous
#include <cuda_runtime.h>
#include <math.h>
#include <stdint.h>
#include <stddef.h>

#define N0V 50000
#define N1V 150000
#define N2V 100000
#define DV  256

// ---- scratch (device globals: no allocation allowed) ----
__device__ float g_xj0[(size_t)N0V * DV];
__device__ float g_xj1[(size_t)N1V * DV];
__device__ float g_xj2[(size_t)N2V * DV];
__device__ float g_ai0[N0V];
__device__ float g_aj0[N0V];
__device__ float g_aj1[N1V];
__device__ float g_aj2[N2V];

__device__ __forceinline__ uint32_t f2tf32(uint32_t bits)
{
    uint32_t r;
    asm("cvt.rna.tf32.f32 %0, %1;" : "=r"(r) : "f"(__uint_as_float(bits)));
    return r;
}

__device__ __forceinline__ void cp16(uint32_t dst, const void* src, bool valid)
{
    const int sz = valid ? 16 : 0;
    asm volatile("cp.async.cg.shared.global [%0], [%1], 16, %2;"
                 :: "r"(dst), "l"(src), "r"(sz));
}

// ============================================================
// Tensor-core GEMM: Y[M,256] = relu(X[M,256] @ W[256,256]^T + b)
// Fused: avec[row] += Y[row,:] . aw + ab
//
// Block tile 128x256 (full N), 8 warps of 64x64. BK=32, cp.async
// double buffered. LDS.128 fragment loads via a shared k-permutation
// (phys k = 8*tig + 4*half + 2*s + h for both A and B) with XOR
// swizzle on 16B chunks -> conflict-free.
// ============================================================
#define BM 128
#define BK 32
#define A_BYTES (BM * BK * 4)          // 16 KB
#define B_BYTES (256 * BK * 4)         // 32 KB
#define STAGE_BYTES (A_BYTES + B_BYTES)
#define SMEM_BYTES (2 * STAGE_BYTES)   // 96 KB

__global__ __launch_bounds__(256, 1)
void gemm_tf32_kernel(const float* __restrict__ X,
                      const float* __restrict__ W,
                      const float* __restrict__ bias,
                      const float* __restrict__ aw,
                      const float* __restrict__ ab,
                      float* __restrict__ Y,
                      float* __restrict__ avec,
                      int M)
{
    extern __shared__ char smem[];
    const uint32_t smem_u32 = (uint32_t)__cvta_generic_to_shared(smem);

    const int t    = threadIdx.x;
    const int wid  = t >> 5;
    const int lane = t & 31;
    const int grp  = lane >> 2;   // 0..7
    const int tig  = lane & 3;    // 0..3
    const int warp_m = wid & 1;   // 64-row half
    const int warp_n = wid >> 1;  // 0..3 -> 64 cols each
    const int bm = blockIdx.x * BM;

    float acc[4][8][4];
#pragma unroll
    for (int mi = 0; mi < 4; mi++)
#pragma unroll
        for (int nj = 0; nj < 8; nj++)
#pragma unroll
            for (int r = 0; r < 4; r++) acc[mi][nj][r] = 0.0f;

    // ---- async tile loader: A 1024 chunks, B 2048 chunks of 16B ----
    auto load_stage = [&](int kt, int stage) {
        const uint32_t abase = smem_u32 + stage * STAGE_BYTES;
        const uint32_t bbase = abase + A_BYTES;
#pragma unroll
        for (int l = 0; l < 4; l++) {
            const int i   = t + l * 256;
            const int row = i >> 3;
            const int c   = i & 7;
            const uint32_t dst = abase + row * 128 + ((c ^ (row & 7)) << 4);
            const float* src = X + (size_t)(bm + row) * DV + kt * BK + c * 4;
            cp16(dst, src, (bm + row) < M);
        }
#pragma unroll
        for (int l = 0; l < 8; l++) {
            const int i   = t + l * 256;
            const int col = i >> 3;
            const int c   = i & 7;
            const uint32_t dst = bbase + col * 128 + ((c ^ (col & 7)) << 4);
            const float* src = W + (size_t)col * DV + kt * BK + c * 4;
            cp16(dst, src, true);
        }
        asm volatile("cp.async.commit_group;");
    };

    load_stage(0, 0);

    const int NKT = DV / BK;  // 8
    for (int kt = 0; kt < NKT; kt++) {
        if (kt + 1 < NKT) {
            load_stage(kt + 1, (kt + 1) & 1);
            asm volatile("cp.async.wait_group 1;");
        } else {
            asm volatile("cp.async.wait_group 0;");
        }
        __syncthreads();

        const char* abase = smem + (kt & 1) * STAGE_BYTES;
        const char* bbase = abase + A_BYTES;

#pragma unroll
        for (int half = 0; half < 2; half++) {
            const int chunk = ((2 * tig + half) ^ grp) << 4;
            uint32_t a[4][2][4];
#pragma unroll
            for (int mi = 0; mi < 4; mi++)
#pragma unroll
                for (int rh = 0; rh < 2; rh++) {
                    const int r = warp_m * 64 + mi * 16 + rh * 8 + grp;
                    const uint4 v = *(const uint4*)(abase + r * 128 + chunk);
                    a[mi][rh][0] = f2tf32(v.x);
                    a[mi][rh][1] = f2tf32(v.y);
                    a[mi][rh][2] = f2tf32(v.z);
                    a[mi][rh][3] = f2tf32(v.w);
                }
            uint32_t b[8][4];
#pragma unroll
            for (int nj = 0; nj < 8; nj++) {
                const int c = warp_n * 64 + nj * 8 + grp;
                const uint4 v = *(const uint4*)(bbase + c * 128 + chunk);
                b[nj][0] = f2tf32(v.x);
                b[nj][1] = f2tf32(v.y);
                b[nj][2] = f2tf32(v.z);
                b[nj][3] = f2tf32(v.w);
            }
#pragma unroll
            for (int s2 = 0; s2 < 2; s2++)
#pragma unroll
                for (int mi = 0; mi < 4; mi++)
#pragma unroll
                    for (int nj = 0; nj < 8; nj++) {
                        asm volatile(
                            "mma.sync.aligned.m16n8k8.row.col.f32.tf32.tf32.f32 "
                            "{%0,%1,%2,%3}, {%4,%5,%6,%7}, {%8,%9}, {%0,%1,%2,%3};"
                            : "+f"(acc[mi][nj][0]), "+f"(acc[mi][nj][1]),
                              "+f"(acc[mi][nj][2]), "+f"(acc[mi][nj][3])
                            : "r"(a[mi][0][2 * s2]), "r"(a[mi][1][2 * s2]),
                              "r"(a[mi][0][2 * s2 + 1]), "r"(a[mi][1][2 * s2 + 1]),
                              "r"(b[nj][2 * s2]), "r"(b[nj][2 * s2 + 1]));
                    }
        }
        __syncthreads();
    }

    // ---- epilogue: +bias, relu, store, fused attention dot ----
    float awv[8][2], bv[8][2];
#pragma unroll
    for (int nj = 0; nj < 8; nj++) {
        const int col = warp_n * 64 + nj * 8 + 2 * tig;
        const float2 a2 = *(const float2*)(aw + col);
        const float2 b2 = *(const float2*)(bias + col);
        awv[nj][0] = a2.x; awv[nj][1] = a2.y;
        bv[nj][0]  = b2.x; bv[nj][1]  = b2.y;
    }
    const float abv = __ldg(ab);
    const bool add_ab = (warp_n == 0);

#pragma unroll
    for (int mi = 0; mi < 4; mi++) {
#pragma unroll
        for (int h = 0; h < 2; h++) {
            const int gr = bm + warp_m * 64 + mi * 16 + grp + h * 8;
            float dp = 0.0f;
            float2 st[8];
#pragma unroll
            for (int nj = 0; nj < 8; nj++) {
                const float v0 = fmaxf(acc[mi][nj][h * 2 + 0] + bv[nj][0], 0.f);
                const float v1 = fmaxf(acc[mi][nj][h * 2 + 1] + bv[nj][1], 0.f);
                dp += v0 * awv[nj][0] + v1 * awv[nj][1];
                st[nj].x = v0; st[nj].y = v1;
            }
            dp += __shfl_xor_sync(0xffffffffu, dp, 1);
            dp += __shfl_xor_sync(0xffffffffu, dp, 2);
            if (gr < M) {
#pragma unroll
                for (int nj = 0; nj < 8; nj++) {
                    const int col = warp_n * 64 + nj * 8 + 2 * tig;
                    *(float2*)(Y + (size_t)gr * DV + col) = st[nj];
                }
                if (tig == 0)
                    atomicAdd(avec + gr, dp + (add_ab ? abv : 0.0f));
            }
        }
    }
}

// ============================================================
// Zero the attention-scalar accumulators (replay-safe)
// ============================================================
__global__ void zero_avec_kernel(float* a, float* b, float* c, float* d)
{
    const int i = blockIdx.x * blockDim.x + threadIdx.x;
    if (i < N0V) { a[i] = 0.f; b[i] = 0.f; }
    if (i < N1V) c[i] = 0.f;
    if (i < N2V) d[i] = 0.f;
}

// ============================================================
// Edge aggregation: out[r,:] += sigmoid(ai[r]+aj[c]) * xj[c,:]
// One warp per edge; red.global.add.v4.f32.
// ============================================================
__device__ __forceinline__ void red_add_v4(float* p, float4 v)
{
    asm volatile("red.global.add.v4.f32 [%0], {%1, %2, %3, %4};"
                 :: "l"(p), "f"(v.x), "f"(v.y), "f"(v.z), "f"(v.w)
                 : "memory");
}

__global__ void edge_kernel(const int* __restrict__ rows,
                            const int* __restrict__ cols,
                            const float* __restrict__ ai,
                            const float* __restrict__ aj,
                            const float* __restrict__ xj,
                            float* __restrict__ out,
                            int E)
{
    const int e    = (int)((blockIdx.x * (unsigned)blockDim.x + threadIdx.x) >> 5);
    const int lane = threadIdx.x & 31;
    if (e >= E) return;

    const int r = __ldg(rows + e);
    const int c = __ldg(cols + e);
    const float s   = __ldg(ai + r) + __ldg(aj + c);
    const float att = 1.0f / (1.0f + __expf(-s));

    const float4* src = (const float4*)(xj + (size_t)c * DV);
    float* dst = out + (size_t)r * DV;

    float4 v0 = __ldg(src + lane);
    float4 v1 = __ldg(src + 32 + lane);
    v0.x *= att; v0.y *= att; v0.z *= att; v0.w *= att;
    v1.x *= att; v1.y *= att; v1.z *= att; v1.w *= att;

    red_add_v4(dst + lane * 4, v0);
    red_add_v4(dst + 128 + lane * 4, v1);
}

// ============================================================
// Launch
// ============================================================
extern "C" void kernel_launch(void* const* d_in, const int* in_sizes, int n_in,
                              void* d_out, int out_size)
{
    const float* x0    = (const float*)d_in[0];
    const float* x1    = (const float*)d_in[1];
    const float* x2    = (const float*)d_in[2];
    const int*   rows0 = (const int*)d_in[3];
    const int*   cols0 = (const int*)d_in[4];
    const int*   rows1 = (const int*)d_in[5];
    const int*   cols1 = (const int*)d_in[6];
    const int*   rows2 = (const int*)d_in[7];
    const int*   cols2 = (const int*)d_in[8];
    const float* W1 = (const float*)d_in[9];
    const float* b1 = (const float*)d_in[10];
    const float* W2 = (const float*)d_in[11];
    const float* b2 = (const float*)d_in[12];
    const float* W3 = (const float*)d_in[13];
    const float* b3 = (const float*)d_in[14];
    const float* W4 = (const float*)d_in[15];
    const float* b4 = (const float*)d_in[16];
    const float* a1w = (const float*)d_in[17];
    const float* a1b = (const float*)d_in[18];
    const float* a2w = (const float*)d_in[19];
    const float* a2b = (const float*)d_in[20];

    const int E0 = in_sizes[3];
    const int E1 = in_sizes[5];
    const int E2 = in_sizes[7];

    float* out = (float*)d_out;

    float *xj0, *xj1, *xj2, *ai0, *aj0, *aj1, *aj2;
    cudaGetSymbolAddress((void**)&xj0, g_xj0);
    cudaGetSymbolAddress((void**)&xj1, g_xj1);
    cudaGetSymbolAddress((void**)&xj2, g_xj2);
    cudaGetSymbolAddress((void**)&ai0, g_ai0);
    cudaGetSymbolAddress((void**)&aj0, g_aj0);
    cudaGetSymbolAddress((void**)&aj1, g_aj1);
    cudaGetSymbolAddress((void**)&aj2, g_aj2);

    static bool attr_set = false;
    if (!attr_set) {
        cudaFuncSetAttribute(gemm_tf32_kernel,
                             cudaFuncAttributeMaxDynamicSharedMemorySize, SMEM_BYTES);
        attr_set = true;
    }

    // 0) zero attention accumulators (graph-replay safe)
    zero_avec_kernel<<<(N1V + 255) / 256, 256>>>(ai0, aj0, aj1, aj2);

    // 1) GEMMs (tensor core tf32, fused attention dot).
    //    Order so xj0 (and out) are the most recent L2 residents when
    //    edge0 (800K edges, gathers xj0 / reds into out) runs.
    gemm_tf32_kernel<<<(N1V + BM - 1) / BM, 256, SMEM_BYTES>>>(x1, W3, b3, a2w, a2b, xj1, aj1, N1V);
    gemm_tf32_kernel<<<(N2V + BM - 1) / BM, 256, SMEM_BYTES>>>(x2, W4, b4, a2w, a2b, xj2, aj2, N2V);
    gemm_tf32_kernel<<<(N0V + BM - 1) / BM, 256, SMEM_BYTES>>>(x0, W1, b1, a1w, a1b, out, ai0, N0V);
    gemm_tf32_kernel<<<(N0V + BM - 1) / BM, 256, SMEM_BYTES>>>(x0, W2, b2, a2w, a2b, xj0, aj0, N0V);

    // 2) edge aggregations (atomic vector adds into d_out); edge0 first (hot L2)
    edge_kernel<<<(int)(((size_t)E0 * 32 + 255) / 256), 256>>>(rows0, cols0, ai0, aj0, xj0, out, E0);
    edge_kernel<<<(int)(((size_t)E1 * 32 + 255) / 256), 256>>>(rows1, cols1, ai0, aj1, xj1, out, E1);
    edge_kernel<<<(int)(((size_t)E2 * 32 + 255) / 256), 256>>>(rows2, cols2, ai0, aj2, xj2, out, E2);
}

// round 4
// speedup vs baseline: 2.0729x; 1.0033x over previous
#include <cuda_runtime.h>
#include <math.h>
#include <stdint.h>
#include <stddef.h>

#define N0V 50000
#define N1V 150000
#define N2V 100000
#define DV  256

// ---- scratch (device globals: no allocation allowed) ----
__device__ float g_xj0[(size_t)N0V * DV];
__device__ float g_xj1[(size_t)N1V * DV];
__device__ float g_xj2[(size_t)N2V * DV];
__device__ float g_ai0[N0V];
__device__ float g_aj0[N0V];
__device__ float g_aj1[N1V];
__device__ float g_aj2[N2V];

__device__ __forceinline__ void cp16(uint32_t dst, const void* src, bool valid)
{
    const int sz = valid ? 16 : 0;
    asm volatile("cp.async.cg.shared.global [%0], [%1], 16, %2;"
                 :: "r"(dst), "l"(src), "r"(sz));
}

// ============================================================
// Tensor-core GEMM: Y[M,256] = relu(X[M,256] @ W[256,256]^T + b)
// Fused: avec[row] += Y[row,:] . aw + ab
//
// Block 128x256 (full N), 512 threads = 16 warps of 64x32.
// BK=32, 3-stage cp.async pipeline. Raw fp32 bits fed to
// mma.tf32 (hardware truncation; no per-fragment cvt).
// XOR-swizzled 16B chunks; shared k-permutation for A and B.
// ============================================================
#define BM 128
#define BK 32
#define NSTAGE 3
#define A_BYTES (BM * BK * 4)          // 16 KB
#define B_BYTES (256 * BK * 4)         // 32 KB
#define STAGE_BYTES (A_BYTES + B_BYTES)
#define SMEM_BYTES (NSTAGE * STAGE_BYTES)   // 144 KB

__global__ __launch_bounds__(512, 1)
void gemm_tf32_kernel(const float* __restrict__ X,
                      const float* __restrict__ W,
                      const float* __restrict__ bias,
                      const float* __restrict__ aw,
                      const float* __restrict__ ab,
                      float* __restrict__ Y,
                      float* __restrict__ avec,
                      int M)
{
    extern __shared__ char smem[];
    const uint32_t smem_u32 = (uint32_t)__cvta_generic_to_shared(smem);

    const int t    = threadIdx.x;
    const int wid  = t >> 5;
    const int lane = t & 31;
    const int grp  = lane >> 2;   // 0..7
    const int tig  = lane & 3;    // 0..3
    const int warp_m = wid & 1;   // 64-row half
    const int warp_n = wid >> 1;  // 0..7 -> 32 cols each
    const int bm = blockIdx.x * BM;

    float acc[4][4][4];
#pragma unroll
    for (int mi = 0; mi < 4; mi++)
#pragma unroll
        for (int nj = 0; nj < 4; nj++)
#pragma unroll
            for (int r = 0; r < 4; r++) acc[mi][nj][r] = 0.0f;

    // ---- async tile loader (A: 1024 16B chunks, B: 2048) ----
    auto load_stage = [&](int kt, int stage) {
        const uint32_t abase = smem_u32 + stage * STAGE_BYTES;
        const uint32_t bbase = abase + A_BYTES;
#pragma unroll
        for (int l = 0; l < 2; l++) {
            const int i   = t + l * 512;
            const int row = i >> 3;
            const int c   = i & 7;
            const uint32_t dst = abase + row * 128 + ((c ^ (row & 7)) << 4);
            const float* src = X + (size_t)(bm + row) * DV + kt * BK + c * 4;
            cp16(dst, src, (bm + row) < M);
        }
#pragma unroll
        for (int l = 0; l < 4; l++) {
            const int i   = t + l * 512;
            const int col = i >> 3;
            const int c   = i & 7;
            const uint32_t dst = bbase + col * 128 + ((c ^ (col & 7)) << 4);
            const float* src = W + (size_t)col * DV + kt * BK + c * 4;
            cp16(dst, src, true);
        }
        asm volatile("cp.async.commit_group;");
    };

    const int NKT = DV / BK;  // 8
    load_stage(0, 0);
    load_stage(1, 1);

    int stage = 0;
    for (int kt = 0; kt < NKT; kt++) {
        if (kt + 2 < NKT) {
            load_stage(kt + 2, (kt + 2) % NSTAGE);
            asm volatile("cp.async.wait_group 2;");
        } else if (kt + 1 < NKT) {
            asm volatile("cp.async.wait_group 1;");
        } else {
            asm volatile("cp.async.wait_group 0;");
        }
        __syncthreads();

        const char* abase = smem + stage * STAGE_BYTES;
        const char* bbase = abase + A_BYTES;
        stage = (stage + 1 == NSTAGE) ? 0 : stage + 1;

#pragma unroll
        for (int half = 0; half < 2; half++) {
            const int chunk = ((2 * tig + half) ^ grp) << 4;
            uint32_t a[4][2][4];
#pragma unroll
            for (int mi = 0; mi < 4; mi++)
#pragma unroll
                for (int rh = 0; rh < 2; rh++) {
                    const int r = warp_m * 64 + mi * 16 + rh * 8 + grp;
                    const uint4 v = *(const uint4*)(abase + r * 128 + chunk);
                    a[mi][rh][0] = v.x; a[mi][rh][1] = v.y;
                    a[mi][rh][2] = v.z; a[mi][rh][3] = v.w;
                }
            uint32_t b[4][4];
#pragma unroll
            for (int nj = 0; nj < 4; nj++) {
                const int c = warp_n * 32 + nj * 8 + grp;
                const uint4 v = *(const uint4*)(bbase + c * 128 + chunk);
                b[nj][0] = v.x; b[nj][1] = v.y;
                b[nj][2] = v.z; b[nj][3] = v.w;
            }
#pragma unroll
            for (int s2 = 0; s2 < 2; s2++)
#pragma unroll
                for (int mi = 0; mi < 4; mi++)
#pragma unroll
                    for (int nj = 0; nj < 4; nj++) {
                        asm volatile(
                            "mma.sync.aligned.m16n8k8.row.col.f32.tf32.tf32.f32 "
                            "{%0,%1,%2,%3}, {%4,%5,%6,%7}, {%8,%9}, {%0,%1,%2,%3};"
                            : "+f"(acc[mi][nj][0]), "+f"(acc[mi][nj][1]),
                              "+f"(acc[mi][nj][2]), "+f"(acc[mi][nj][3])
                            : "r"(a[mi][0][2 * s2]), "r"(a[mi][1][2 * s2]),
                              "r"(a[mi][0][2 * s2 + 1]), "r"(a[mi][1][2 * s2 + 1]),
                              "r"(b[nj][2 * s2]), "r"(b[nj][2 * s2 + 1]));
                    }
        }
        __syncthreads();
    }

    // ---- epilogue: +bias, relu, store, fused attention dot ----
    float awv[4][2], bv[4][2];
#pragma unroll
    for (int nj = 0; nj < 4; nj++) {
        const int col = warp_n * 32 + nj * 8 + 2 * tig;
        const float2 a2 = *(const float2*)(aw + col);
        const float2 b2 = *(const float2*)(bias + col);
        awv[nj][0] = a2.x; awv[nj][1] = a2.y;
        bv[nj][0]  = b2.x; bv[nj][1]  = b2.y;
    }
    const float abv = __ldg(ab);
    const bool add_ab = (warp_n == 0);

#pragma unroll
    for (int mi = 0; mi < 4; mi++) {
#pragma unroll
        for (int h = 0; h < 2; h++) {
            const int gr = bm + warp_m * 64 + mi * 16 + grp + h * 8;
            float dp = 0.0f;
            float2 st[4];
#pragma unroll
            for (int nj = 0; nj < 4; nj++) {
                const float v0 = fmaxf(acc[mi][nj][h * 2 + 0] + bv[nj][0], 0.f);
                const float v1 = fmaxf(acc[mi][nj][h * 2 + 1] + bv[nj][1], 0.f);
                dp += v0 * awv[nj][0] + v1 * awv[nj][1];
                st[nj].x = v0; st[nj].y = v1;
            }
            dp += __shfl_xor_sync(0xffffffffu, dp, 1);
            dp += __shfl_xor_sync(0xffffffffu, dp, 2);
            if (gr < M) {
#pragma unroll
                for (int nj = 0; nj < 4; nj++) {
                    const int col = warp_n * 32 + nj * 8 + 2 * tig;
                    *(float2*)(Y + (size_t)gr * DV + col) = st[nj];
                }
                if (tig == 0)
                    atomicAdd(avec + gr, dp + (add_ab ? abv : 0.0f));
            }
        }
    }
}

// ============================================================
// Zero the attention-scalar accumulators (replay-safe)
// ============================================================
__global__ void zero_avec_kernel(float* a, float* b, float* c, float* d)
{
    const int i = blockIdx.x * blockDim.x + threadIdx.x;
    if (i < N0V) { a[i] = 0.f; b[i] = 0.f; }
    if (i < N1V) c[i] = 0.f;
    if (i < N2V) d[i] = 0.f;
}

// ============================================================
// Edge aggregation: out[r,:] += sigmoid(ai[r]+aj[c]) * xj[c,:]
// One warp per edge; red.global.add.v4.f32.
// ============================================================
__device__ __forceinline__ void red_add_v4(float* p, float4 v)
{
    asm volatile("red.global.add.v4.f32 [%0], {%1, %2, %3, %4};"
                 :: "l"(p), "f"(v.x), "f"(v.y), "f"(v.z), "f"(v.w)
                 : "memory");
}

__global__ void edge_kernel(const int* __restrict__ rows,
                            const int* __restrict__ cols,
                            const float* __restrict__ ai,
                            const float* __restrict__ aj,
                            const float* __restrict__ xj,
                            float* __restrict__ out,
                            int E)
{
    const int e    = (int)((blockIdx.x * (unsigned)blockDim.x + threadIdx.x) >> 5);
    const int lane = threadIdx.x & 31;
    if (e >= E) return;

    const int r = __ldg(rows + e);
    const int c = __ldg(cols + e);
    const float s   = __ldg(ai + r) + __ldg(aj + c);
    const float att = 1.0f / (1.0f + __expf(-s));

    const float4* src = (const float4*)(xj + (size_t)c * DV);
    float* dst = out + (size_t)r * DV;

    float4 v0 = __ldg(src + lane);
    float4 v1 = __ldg(src + 32 + lane);
    v0.x *= att; v0.y *= att; v0.z *= att; v0.w *= att;
    v1.x *= att; v1.y *= att; v1.z *= att; v1.w *= att;

    red_add_v4(dst + lane * 4, v0);
    red_add_v4(dst + 128 + lane * 4, v1);
}

// ============================================================
// Launch
// ============================================================
extern "C" void kernel_launch(void* const* d_in, const int* in_sizes, int n_in,
                              void* d_out, int out_size)
{
    const float* x0    = (const float*)d_in[0];
    const float* x1    = (const float*)d_in[1];
    const float* x2    = (const float*)d_in[2];
    const int*   rows0 = (const int*)d_in[3];
    const int*   cols0 = (const int*)d_in[4];
    const int*   rows1 = (const int*)d_in[5];
    const int*   cols1 = (const int*)d_in[6];
    const int*   rows2 = (const int*)d_in[7];
    const int*   cols2 = (const int*)d_in[8];
    const float* W1 = (const float*)d_in[9];
    const float* b1 = (const float*)d_in[10];
    const float* W2 = (const float*)d_in[11];
    const float* b2 = (const float*)d_in[12];
    const float* W3 = (const float*)d_in[13];
    const float* b3 = (const float*)d_in[14];
    const float* W4 = (const float*)d_in[15];
    const float* b4 = (const float*)d_in[16];
    const float* a1w = (const float*)d_in[17];
    const float* a1b = (const float*)d_in[18];
    const float* a2w = (const float*)d_in[19];
    const float* a2b = (const float*)d_in[20];

    const int E0 = in_sizes[3];
    const int E1 = in_sizes[5];
    const int E2 = in_sizes[7];

    float* out = (float*)d_out;

    float *xj0, *xj1, *xj2, *ai0, *aj0, *aj1, *aj2;
    cudaGetSymbolAddress((void**)&xj0, g_xj0);
    cudaGetSymbolAddress((void**)&xj1, g_xj1);
    cudaGetSymbolAddress((void**)&xj2, g_xj2);
    cudaGetSymbolAddress((void**)&ai0, g_ai0);
    cudaGetSymbolAddress((void**)&aj0, g_aj0);
    cudaGetSymbolAddress((void**)&aj1, g_aj1);
    cudaGetSymbolAddress((void**)&aj2, g_aj2);

    static bool attr_set = false;
    if (!attr_set) {
        cudaFuncSetAttribute(gemm_tf32_kernel,
                             cudaFuncAttributeMaxDynamicSharedMemorySize, SMEM_BYTES);
        attr_set = true;
    }

    // 0) zero attention accumulators (graph-replay safe)
    zero_avec_kernel<<<(N1V + 255) / 256, 256>>>(ai0, aj0, aj1, aj2);

    // 1) GEMMs (tensor core tf32, fused attention dot).
    //    Order so xj0/out are freshest in L2 when edge0 runs.
    gemm_tf32_kernel<<<(N1V + BM - 1) / BM, 512, SMEM_BYTES>>>(x1, W3, b3, a2w, a2b, xj1, aj1, N1V);
    gemm_tf32_kernel<<<(N2V + BM - 1) / BM, 512, SMEM_BYTES>>>(x2, W4, b4, a2w, a2b, xj2, aj2, N2V);
    gemm_tf32_kernel<<<(N0V + BM - 1) / BM, 512, SMEM_BYTES>>>(x0, W1, b1, a1w, a1b, out, ai0, N0V);
    gemm_tf32_kernel<<<(N0V + BM - 1) / BM, 512, SMEM_BYTES>>>(x0, W2, b2, a2w, a2b, xj0, aj0, N0V);

    // 2) edge aggregations (atomic vector adds into d_out); edge0 first (hot L2)
    edge_kernel<<<(int)(((size_t)E0 * 32 + 255) / 256), 256>>>(rows0, cols0, ai0, aj0, xj0, out, E0);
    edge_kernel<<<(int)(((size_t)E1 * 32 + 255) / 256), 256>>>(rows1, cols1, ai0, aj1, xj1, out, E1);
    edge_kernel<<<(int)(((size_t)E2 * 32 + 255) / 256), 256>>>(rows2, cols2, ai0, aj2, xj2, out, E2);
}